// round 3
// baseline (speedup 1.0000x reference)
#include <cuda_runtime.h>
#include <cuda_bf16.h>
#include <cstdint>

#define NB 256
#define NS 256
#define ND 256
#define NH 4
#define DH 64

// ---------------------------------------------------------------------------
// Device scratch (~34 MB total)
// ---------------------------------------------------------------------------
__device__ __nv_bfloat16 g_ctx[NB * NS * ND];       // [b*s][d]
__device__ __nv_bfloat16 g_WqkvT[3 * ND * ND];      // [mat*256+n][k]  (0=Q,1=K,2=V)
__device__ __nv_bfloat16 g_WoT[ND * ND];            // [n][k]
__device__ int g_rank[NB];
__device__ int g_big[NB];

// ---------------------------------------------------------------------------
// PTX helpers
// ---------------------------------------------------------------------------
__device__ __forceinline__ uint32_t sptr(const void* p) {
    return static_cast<uint32_t>(__cvta_generic_to_shared(p));
}
__device__ __forceinline__ void ldm_x4(uint32_t r[4], uint32_t a) {
    asm volatile("ldmatrix.sync.aligned.m8n8.x4.shared.b16 {%0,%1,%2,%3}, [%4];\n"
                 : "=r"(r[0]), "=r"(r[1]), "=r"(r[2]), "=r"(r[3]) : "r"(a));
}
__device__ __forceinline__ void ldm_x2(uint32_t r[2], uint32_t a) {
    asm volatile("ldmatrix.sync.aligned.m8n8.x2.shared.b16 {%0,%1}, [%2];\n"
                 : "=r"(r[0]), "=r"(r[1]) : "r"(a));
}
__device__ __forceinline__ void ldm_x2t(uint32_t r[2], uint32_t a) {
    asm volatile("ldmatrix.sync.aligned.m8n8.x2.trans.shared.b16 {%0,%1}, [%2];\n"
                 : "=r"(r[0]), "=r"(r[1]) : "r"(a));
}
__device__ __forceinline__ void mma16816(float c[4], const uint32_t a[4], const uint32_t b[2]) {
    asm volatile(
        "mma.sync.aligned.m16n8k16.row.col.f32.bf16.bf16.f32 "
        "{%0,%1,%2,%3}, {%4,%5,%6,%7}, {%8,%9}, {%0,%1,%2,%3};\n"
        : "+f"(c[0]), "+f"(c[1]), "+f"(c[2]), "+f"(c[3])
        : "r"(a[0]), "r"(a[1]), "r"(a[2]), "r"(a[3]), "r"(b[0]), "r"(b[1]));
}
__device__ __forceinline__ uint32_t packbf(float x, float y) {
    __nv_bfloat162 t = __floats2bfloat162_rn(x, y);
    return *reinterpret_cast<uint32_t*>(&t);
}
__device__ __forceinline__ float fexp2(float x) {
    float y;
    asm("ex2.approx.ftz.f32 %0, %1;" : "=f"(y) : "f"(x));
    return y;
}

// ---------------------------------------------------------------------------
// prep kernels
// ---------------------------------------------------------------------------
__global__ void prep_rank(const int* __restrict__ ids, int max_obj) {
    __shared__ int sh[NB];
    int t = threadIdx.x;
    sh[t] = ids[t];
    __syncthreads();
    int id = sh[t];
    int rank = 0, size = 0;
    #pragma unroll 8
    for (int j = 0; j < NB; j++) {
        int same = (sh[j] == id);
        size += same;
        rank += (j < t) ? same : 0;
    }
    g_rank[t] = (rank < max_obj) ? rank : (max_obj - 1);
    g_big[t]  = (size > 1);
}

__global__ void conv_weights(const float* __restrict__ Wq, const float* __restrict__ Wk,
                             const float* __restrict__ Wv, const float* __restrict__ Wo) {
    int idx = blockIdx.x * 256 + threadIdx.x;     // [0, 3*65536)
    int row = idx >> 8;
    int kk  = idx & 255;
    int mat = row >> 8;
    int n   = row & 255;
    const float* W = (mat == 0) ? Wq : ((mat == 1) ? Wk : Wv);
    g_WqkvT[idx] = __float2bfloat16(W[kk * ND + n]);
    if (idx < ND * ND)
        g_WoT[idx] = __float2bfloat16(Wo[(idx & 255) * ND + (idx >> 8)]);
}

// ---------------------------------------------------------------------------
// Fused kernel: one block per (b,h), 512 threads = 16 warps, 16 q-rows/warp.
// smem: As[256][40] + Bs3[3][64][264] + Ks[256][72] + Vs[256][72] + add[256]
//       20480 + 101376 + 36864 + 36864 + 1024 = 196608 B
// ---------------------------------------------------------------------------
#define AS_OFF   0
#define BS3_OFF  20480
#define KS_OFF   121856
#define VS_OFF   158720
#define ADD_OFF  195584
#define FUSED_SMEM 196608

__device__ __forceinline__ void stage_A(__nv_bfloat16 (*As)[40], const float* __restrict__ src,
                                        const float* __restrict__ addsm, int kt, int tid) {
    int row = tid >> 1;
    int cg  = (tid & 1) * 16;
    const float* gsrc = src + row * ND + kt * 32 + cg;
    const float* av   = addsm + kt * 32 + cg;
    float4 x0 = *reinterpret_cast<const float4*>(gsrc);
    float4 x1 = *reinterpret_cast<const float4*>(gsrc + 4);
    float4 x2 = *reinterpret_cast<const float4*>(gsrc + 8);
    float4 x3 = *reinterpret_cast<const float4*>(gsrc + 12);
    float4 a0 = *reinterpret_cast<const float4*>(av);
    float4 a1 = *reinterpret_cast<const float4*>(av + 4);
    float4 a2 = *reinterpret_cast<const float4*>(av + 8);
    float4 a3 = *reinterpret_cast<const float4*>(av + 12);
    uint4 p0, p1;
    p0.x = packbf(x0.x + a0.x, x0.y + a0.y);
    p0.y = packbf(x0.z + a0.z, x0.w + a0.w);
    p0.z = packbf(x1.x + a1.x, x1.y + a1.y);
    p0.w = packbf(x1.z + a1.z, x1.w + a1.w);
    p1.x = packbf(x2.x + a2.x, x2.y + a2.y);
    p1.y = packbf(x2.z + a2.z, x2.w + a2.w);
    p1.z = packbf(x3.x + a3.x, x3.y + a3.y);
    p1.w = packbf(x3.z + a3.z, x3.w + a3.w);
    *reinterpret_cast<uint4*>(&As[row][cg])     = p0;
    *reinterpret_cast<uint4*>(&As[row][cg + 8]) = p1;
}

__global__ __launch_bounds__(512, 1) void fused_bh(const float* __restrict__ bs,
                                                   const float* __restrict__ obj,
                                                   const float* __restrict__ scale,
                                                   const float* __restrict__ bq,
                                                   const float* __restrict__ bk,
                                                   const float* __restrict__ bv) {
    extern __shared__ char smraw[];
    __nv_bfloat16 (*As)[40]      = reinterpret_cast<__nv_bfloat16(*)[40]>(smraw + AS_OFF);
    __nv_bfloat16 (*Bs3)[64][264] = reinterpret_cast<__nv_bfloat16(*)[64][264]>(smraw + BS3_OFF);
    __nv_bfloat16 (*Ks)[72]      = reinterpret_cast<__nv_bfloat16(*)[72]>(smraw + KS_OFF);
    __nv_bfloat16 (*Vs)[72]      = reinterpret_cast<__nv_bfloat16(*)[72]>(smraw + VS_OFF);
    float* addsm                 = reinterpret_cast<float*>(smraw + ADD_OFF);

    const int bh = blockIdx.x;
    const int b = bh >> 2, h = bh & 3;
    const int tid = threadIdx.x, lane = tid & 31, warp = tid >> 5;
    const int g = lane >> 2, tig = lane & 3;
    const int li = lane & 7, sel = lane >> 3, l16 = lane & 15;
    const float* src = bs + (size_t)b * NS * ND;

    // ---- preload weights (Bs3: 0=K, 1=V, 2=Q slices, [n 0..63][k 0..255]) ----
    #pragma unroll
    for (int i = 0; i < 12; i++) {
        int idx = i * 512 + tid;            // 6144 uint4 total
        int mat = idx >> 11;                // 2048 uint4 per mat
        int rem = idx & 2047;
        int r = rem >> 5;
        int c = (rem & 31) * 8;
        int grow = ((mat == 2) ? 0 : (mat + 1) * 256) + h * DH + r;   // K,V,Q
        *reinterpret_cast<uint4*>(&Bs3[mat][r][c]) =
            *reinterpret_cast<const uint4*>(&g_WqkvT[(size_t)grow * ND + c]);
    }
    if (tid < 256)
        addsm[tid] = scale[0] * obj[g_rank[b] * ND + tid];
    __syncthreads();

    // ---------------- K & V GEMMs (fused A pass) ----------------
    float accK[8][4], accV[8][4];
    #pragma unroll
    for (int j = 0; j < 8; j++)
        #pragma unroll
        for (int c = 0; c < 4; c++) { accK[j][c] = 0.f; accV[j][c] = 0.f; }

    #pragma unroll 1
    for (int kt = 0; kt < 8; kt++) {
        __syncthreads();
        stage_A(As, src, addsm, kt, tid);
        __syncthreads();
        #pragma unroll
        for (int ks = 0; ks < 2; ks++) {
            uint32_t a[4];
            ldm_x4(a, sptr(&As[warp * 16 + (sel & 1) * 8 + li][ks * 16 + (sel >> 1) * 8]));
            #pragma unroll
            for (int nj = 0; nj < 8; nj++) {
                uint32_t bf0[2], bf1[2];
                ldm_x2(bf0, sptr(&Bs3[0][nj * 8 + li][kt * 32 + ks * 16 + (l16 >> 3) * 8]));
                mma16816(accK[nj], a, bf0);
                ldm_x2(bf1, sptr(&Bs3[1][nj * 8 + li][kt * 32 + ks * 16 + (l16 >> 3) * 8]));
                mma16816(accV[nj], a, bf1);
            }
        }
    }
    // epilogue: bias + write K,V to smem
    #pragma unroll
    for (int nj = 0; nj < 8; nj++)
        #pragma unroll
        for (int p = 0; p < 2; p++) {
            int row = warp * 16 + p * 8 + g;
            int col = nj * 8 + tig * 2;
            float bk0 = bk[h * DH + col], bk1 = bk[h * DH + col + 1];
            float bv0 = bv[h * DH + col], bv1 = bv[h * DH + col + 1];
            *reinterpret_cast<__nv_bfloat162*>(&Ks[row][col]) =
                __floats2bfloat162_rn(accK[nj][p * 2] + bk0, accK[nj][p * 2 + 1] + bk1);
            *reinterpret_cast<__nv_bfloat162*>(&Vs[row][col]) =
                __floats2bfloat162_rn(accV[nj][p * 2] + bv0, accV[nj][p * 2 + 1] + bv1);
        }

    // ---------------- Q GEMM ----------------
    float accQ[8][4];
    #pragma unroll
    for (int j = 0; j < 8; j++)
        #pragma unroll
        for (int c = 0; c < 4; c++) accQ[j][c] = 0.f;

    #pragma unroll 1
    for (int kt = 0; kt < 8; kt++) {
        __syncthreads();
        stage_A(As, src, addsm, kt, tid);
        __syncthreads();
        #pragma unroll
        for (int ks = 0; ks < 2; ks++) {
            uint32_t a[4];
            ldm_x4(a, sptr(&As[warp * 16 + (sel & 1) * 8 + li][ks * 16 + (sel >> 1) * 8]));
            #pragma unroll
            for (int nj = 0; nj < 8; nj++) {
                uint32_t bf0[2];
                ldm_x2(bf0, sptr(&Bs3[2][nj * 8 + li][kt * 32 + ks * 16 + (l16 >> 3) * 8]));
                mma16816(accQ[nj], a, bf0);
            }
        }
    }
    // pack Q into A-fragments (bias folded in)
    uint32_t qf[4][4];
    #pragma unroll
    for (int kd = 0; kd < 4; kd++) {
        float b0 = bq[h * DH + kd * 16 + tig * 2];
        float b1 = bq[h * DH + kd * 16 + tig * 2 + 1];
        float b2 = bq[h * DH + kd * 16 + 8 + tig * 2];
        float b3 = bq[h * DH + kd * 16 + 8 + tig * 2 + 1];
        qf[kd][0] = packbf(accQ[2 * kd][0] + b0, accQ[2 * kd][1] + b1);
        qf[kd][1] = packbf(accQ[2 * kd][2] + b0, accQ[2 * kd][3] + b1);
        qf[kd][2] = packbf(accQ[2 * kd + 1][0] + b2, accQ[2 * kd + 1][1] + b3);
        qf[kd][3] = packbf(accQ[2 * kd + 1][2] + b2, accQ[2 * kd + 1][3] + b3);
    }

    // ---------------- flash attention ----------------
    float O[8][4];
    #pragma unroll
    for (int j = 0; j < 8; j++)
        #pragma unroll
        for (int c = 0; c < 4; c++) O[j][c] = 0.f;
    float mrow[2] = {-1e30f, -1e30f};
    float lrow[2] = {0.f, 0.f};
    const float SC = 0.125f * 1.4426950408889634f;

    #pragma unroll 1
    for (int kc = 0; kc < 4; kc++) {
        float s[8][4];
        #pragma unroll
        for (int j = 0; j < 8; j++)
            #pragma unroll
            for (int c = 0; c < 4; c++) s[j][c] = 0.f;

        #pragma unroll
        for (int kd = 0; kd < 4; kd++)
            #pragma unroll
            for (int nj = 0; nj < 8; nj++) {
                uint32_t bfr[2];
                ldm_x2(bfr, sptr(&Ks[kc * 64 + nj * 8 + li][kd * 16 + (l16 >> 3) * 8]));
                mma16816(s[nj], qf[kd], bfr);
            }

        #pragma unroll
        for (int rs = 0; rs < 2; rs++) {
            float mx = -1e30f;
            #pragma unroll
            for (int nj = 0; nj < 8; nj++)
                mx = fmaxf(mx, fmaxf(s[nj][rs * 2], s[nj][rs * 2 + 1]));
            mx = fmaxf(mx, __shfl_xor_sync(0xffffffffu, mx, 1));
            mx = fmaxf(mx, __shfl_xor_sync(0xffffffffu, mx, 2));
            float mnew = fmaxf(mrow[rs], mx);
            float alpha = fexp2((mrow[rs] - mnew) * SC);
            mrow[rs] = mnew;
            float sum = 0.f;
            #pragma unroll
            for (int nj = 0; nj < 8; nj++) {
                float p0 = fexp2((s[nj][rs * 2]     - mnew) * SC);
                float p1 = fexp2((s[nj][rs * 2 + 1] - mnew) * SC);
                s[nj][rs * 2] = p0;
                s[nj][rs * 2 + 1] = p1;
                sum += p0 + p1;
            }
            sum += __shfl_xor_sync(0xffffffffu, sum, 1);
            sum += __shfl_xor_sync(0xffffffffu, sum, 2);
            lrow[rs] = lrow[rs] * alpha + sum;
            #pragma unroll
            for (int nj = 0; nj < 8; nj++) {
                O[nj][rs * 2]     *= alpha;
                O[nj][rs * 2 + 1] *= alpha;
            }
        }

        #pragma unroll
        for (int kk = 0; kk < 4; kk++) {
            uint32_t pa[4];
            pa[0] = packbf(s[2 * kk][0],     s[2 * kk][1]);
            pa[1] = packbf(s[2 * kk][2],     s[2 * kk][3]);
            pa[2] = packbf(s[2 * kk + 1][0], s[2 * kk + 1][1]);
            pa[3] = packbf(s[2 * kk + 1][2], s[2 * kk + 1][3]);
            #pragma unroll
            for (int nj = 0; nj < 8; nj++) {
                uint32_t bv2[2];
                ldm_x2t(bv2, sptr(&Vs[kc * 64 + kk * 16 + l16][nj * 8]));
                mma16816(O[nj], pa, bv2);
            }
        }
    }

    // write ctx
    #pragma unroll
    for (int rs = 0; rs < 2; rs++) {
        float inv = 1.f / lrow[rs];
        int row = warp * 16 + rs * 8 + g;
        #pragma unroll
        for (int nj = 0; nj < 8; nj++) {
            int col = nj * 8 + tig * 2;
            *reinterpret_cast<__nv_bfloat162*>(
                &g_ctx[((size_t)b * NS + row) * ND + h * DH + col]) =
                __floats2bfloat162_rn(O[nj][rs * 2] * inv, O[nj][rs * 2 + 1] * inv);
        }
    }
}

// ---------------------------------------------------------------------------
// Output projection: out = (gsize>1) ? batch_seq + ctx@Wo + bo : batch_seq
// ---------------------------------------------------------------------------
__device__ __forceinline__ void mm_tile(const __nv_bfloat16* __restrict__ A,
                                        const __nv_bfloat16* __restrict__ Bt,
                                        float acc[2][8][4]) {
    __shared__ __nv_bfloat16 Asm[128][40];
    __shared__ __nv_bfloat16 Bsm[128][40];
    const int tid  = threadIdx.x;
    const int lane = tid & 31;
    const int warp = tid >> 5;
    const int wm = warp >> 1, wn = warp & 1;
    const int r0 = tid >> 2, c0 = (tid & 3) * 8;
    const int li = lane & 7, sel = lane >> 3, l16 = lane & 15;

    for (int kt = 0; kt < 8; kt++) {
        const __nv_bfloat16* Ag = A + kt * 32;
        const __nv_bfloat16* Bg = Bt + kt * 32;
        *reinterpret_cast<uint4*>(&Asm[r0][c0])      = *reinterpret_cast<const uint4*>(&Ag[r0 * 256 + c0]);
        *reinterpret_cast<uint4*>(&Asm[r0 + 64][c0]) = *reinterpret_cast<const uint4*>(&Ag[(r0 + 64) * 256 + c0]);
        *reinterpret_cast<uint4*>(&Bsm[r0][c0])      = *reinterpret_cast<const uint4*>(&Bg[r0 * 256 + c0]);
        *reinterpret_cast<uint4*>(&Bsm[r0 + 64][c0]) = *reinterpret_cast<const uint4*>(&Bg[(r0 + 64) * 256 + c0]);
        __syncthreads();
        #pragma unroll
        for (int ks = 0; ks < 2; ks++) {
            uint32_t a[2][4];
            ldm_x4(a[0], sptr(&Asm[wm * 32 +      li + (sel & 1) * 8][ks * 16 + (sel >> 1) * 8]));
            ldm_x4(a[1], sptr(&Asm[wm * 32 + 16 + li + (sel & 1) * 8][ks * 16 + (sel >> 1) * 8]));
            #pragma unroll
            for (int nj = 0; nj < 8; nj++) {
                uint32_t bfr[2];
                ldm_x2(bfr, sptr(&Bsm[wn * 64 + nj * 8 + li][ks * 16 + (l16 >> 3) * 8]));
                mma16816(acc[0][nj], a[0], bfr);
                mma16816(acc[1][nj], a[1], bfr);
            }
        }
        __syncthreads();
    }
}

__global__ __launch_bounds__(256) void gemm_out(const float* __restrict__ bs,
                                                const float* __restrict__ bo,
                                                float* __restrict__ out) {
    float acc[2][8][4];
    #pragma unroll
    for (int i = 0; i < 2; i++)
        #pragma unroll
        for (int j = 0; j < 8; j++)
            #pragma unroll
            for (int c = 0; c < 4; c++) acc[i][j][c] = 0.f;

    const int m0 = blockIdx.x * 128;
    const int n0 = blockIdx.y * 128;
    mm_tile(g_ctx + (size_t)m0 * 256, g_WoT + (size_t)n0 * 256, acc);

    const int lane = threadIdx.x & 31, warp = threadIdx.x >> 5;
    const int wm = warp >> 1, wn = warp & 1;
    const int g = lane >> 2, tig = lane & 3;
    const int big = g_big[m0 >> 8];
    #pragma unroll
    for (int mi = 0; mi < 2; mi++)
        #pragma unroll
        for (int nj = 0; nj < 8; nj++)
            #pragma unroll
            for (int p = 0; p < 2; p++) {
                int m = m0 + wm * 32 + mi * 16 + p * 8 + g;
                int n = n0 + wn * 64 + nj * 8 + tig * 2;
                int idx = m * ND + n;
                float2 base = *reinterpret_cast<const float2*>(&bs[idx]);
                float2 o;
                if (big) {
                    o.x = base.x + acc[mi][nj][p * 2]     + bo[n];
                    o.y = base.y + acc[mi][nj][p * 2 + 1] + bo[n + 1];
                } else {
                    o = base;
                }
                *reinterpret_cast<float2*>(&out[idx]) = o;
            }
}

// ---------------------------------------------------------------------------
// Launch
// ---------------------------------------------------------------------------
extern "C" void kernel_launch(void* const* d_in, const int* in_sizes, int n_in,
                              void* d_out, int out_size) {
    const float* bs    = (const float*)d_in[0];
    const int*   ids   = (const int*)d_in[1];
    const float* Wq    = (const float*)d_in[2];
    const float* Wk    = (const float*)d_in[3];
    const float* Wv    = (const float*)d_in[4];
    const float* Wo    = (const float*)d_in[5];
    const float* bq    = (const float*)d_in[6];
    const float* bk    = (const float*)d_in[7];
    const float* bv    = (const float*)d_in[8];
    const float* bo    = (const float*)d_in[9];
    const float* obj   = (const float*)d_in[10];
    const float* scale = (const float*)d_in[11];
    const int max_obj = in_sizes[10] / ND;

    static bool configured = false;
    if (!configured) {
        cudaFuncSetAttribute(fused_bh, cudaFuncAttributeMaxDynamicSharedMemorySize, FUSED_SMEM);
        configured = true;
    }

    prep_rank<<<1, NB>>>(ids, max_obj);
    conv_weights<<<768, 256>>>(Wq, Wk, Wv, Wo);
    fused_bh<<<NB * NH, 512, FUSED_SMEM>>>(bs, obj, scale, bq, bk, bv);
    gemm_out<<<dim3(512, 2), 256>>>(bs, bo, (float*)d_out);
}

// round 4
// speedup vs baseline: 1.4030x; 1.4030x over previous
#include <cuda_runtime.h>
#include <cuda_bf16.h>
#include <cstdint>

#define NB 256
#define NS 256
#define ND 256
#define NH 4
#define DH 64

// ---------------------------------------------------------------------------
// Device scratch (~34 MB total)
// ---------------------------------------------------------------------------
__device__ __nv_bfloat16 g_ctx[NB * NS * ND];       // [b*s][d]
__device__ __nv_bfloat16 g_WqkvT[3 * ND * ND];      // [mat*256+n][k]  (0=Q,1=K,2=V)
__device__ __nv_bfloat16 g_WoT[ND * ND];            // [n][k]
__device__ int g_rank[NB];
__device__ int g_big[NB];

// ---------------------------------------------------------------------------
// PTX helpers
// ---------------------------------------------------------------------------
__device__ __forceinline__ uint32_t sptr(const void* p) {
    return static_cast<uint32_t>(__cvta_generic_to_shared(p));
}
__device__ __forceinline__ void ldm_x4(uint32_t r[4], uint32_t a) {
    asm volatile("ldmatrix.sync.aligned.m8n8.x4.shared.b16 {%0,%1,%2,%3}, [%4];\n"
                 : "=r"(r[0]), "=r"(r[1]), "=r"(r[2]), "=r"(r[3]) : "r"(a));
}
__device__ __forceinline__ void ldm_x2(uint32_t r[2], uint32_t a) {
    asm volatile("ldmatrix.sync.aligned.m8n8.x2.shared.b16 {%0,%1}, [%2];\n"
                 : "=r"(r[0]), "=r"(r[1]) : "r"(a));
}
__device__ __forceinline__ void ldm_x2t(uint32_t r[2], uint32_t a) {
    asm volatile("ldmatrix.sync.aligned.m8n8.x2.trans.shared.b16 {%0,%1}, [%2];\n"
                 : "=r"(r[0]), "=r"(r[1]) : "r"(a));
}
__device__ __forceinline__ void mma16816(float c[4], const uint32_t a[4], const uint32_t b[2]) {
    asm volatile(
        "mma.sync.aligned.m16n8k16.row.col.f32.bf16.bf16.f32 "
        "{%0,%1,%2,%3}, {%4,%5,%6,%7}, {%8,%9}, {%0,%1,%2,%3};\n"
        : "+f"(c[0]), "+f"(c[1]), "+f"(c[2]), "+f"(c[3])
        : "r"(a[0]), "r"(a[1]), "r"(a[2]), "r"(a[3]), "r"(b[0]), "r"(b[1]));
}
__device__ __forceinline__ uint32_t packbf(float x, float y) {
    __nv_bfloat162 t = __floats2bfloat162_rn(x, y);
    return *reinterpret_cast<uint32_t*>(&t);
}
__device__ __forceinline__ float fexp2(float x) {
    float y;
    asm("ex2.approx.ftz.f32 %0, %1;" : "=f"(y) : "f"(x));
    return y;
}
__device__ __forceinline__ void cpa16(uint32_t dst, const void* src) {
    asm volatile("cp.async.ca.shared.global [%0], [%1], 16;\n" :: "r"(dst), "l"(src));
}
__device__ __forceinline__ void cpcommit() {
    asm volatile("cp.async.commit_group;\n");
}
template <int N> __device__ __forceinline__ void cpwait() {
    asm volatile("cp.async.wait_group %0;\n" :: "n"(N));
}

// ---------------------------------------------------------------------------
// prep kernels
// ---------------------------------------------------------------------------
__global__ void prep_rank(const int* __restrict__ ids, int max_obj) {
    __shared__ int sh[NB];
    int t = threadIdx.x;
    sh[t] = ids[t];
    __syncthreads();
    int id = sh[t];
    int rank = 0, size = 0;
    #pragma unroll 8
    for (int j = 0; j < NB; j++) {
        int same = (sh[j] == id);
        size += same;
        rank += (j < t) ? same : 0;
    }
    g_rank[t] = (rank < max_obj) ? rank : (max_obj - 1);
    g_big[t]  = (size > 1);
}

__global__ void conv_weights(const float* __restrict__ Wq, const float* __restrict__ Wk,
                             const float* __restrict__ Wv, const float* __restrict__ Wo) {
    int idx = blockIdx.x * 256 + threadIdx.x;     // [0, 3*65536)
    int row = idx >> 8;
    int kk  = idx & 255;
    int mat = row >> 8;
    int n   = row & 255;
    const float* W = (mat == 0) ? Wq : ((mat == 1) ? Wk : Wv);
    g_WqkvT[idx] = __float2bfloat16(W[kk * ND + n]);
    if (idx < ND * ND)
        g_WoT[idx] = __float2bfloat16(Wo[(idx & 255) * ND + (idx >> 8)]);
}

// ---------------------------------------------------------------------------
// Fused kernel: one block per (b,h), 512 threads = 16 warps, 16 q-rows/warp.
// Es resident in smem (built ONCE); K+V GEMMs fused in a single Es pass.
// smem: Es[256][264] 135168 + Ks[256][72] 36864 + Vs[256][72] 36864
//       + Bs[2][64][72] 18432  = 227328 B
// ---------------------------------------------------------------------------
#define ES_OFF 0
#define KS_OFF 135168
#define VS_OFF 172032
#define BS_OFF 208896
#define FUSED_SMEM 227328

__global__ __launch_bounds__(512, 1) void fused_bh(const float* __restrict__ bs,
                                                   const float* __restrict__ obj,
                                                   const float* __restrict__ scale,
                                                   const float* __restrict__ bq,
                                                   const float* __restrict__ bk,
                                                   const float* __restrict__ bv) {
    extern __shared__ char smraw[];
    __nv_bfloat16 (*Es)[264]    = reinterpret_cast<__nv_bfloat16(*)[264]>(smraw + ES_OFF);
    __nv_bfloat16 (*Ks)[72]     = reinterpret_cast<__nv_bfloat16(*)[72]>(smraw + KS_OFF);
    __nv_bfloat16 (*Vs)[72]     = reinterpret_cast<__nv_bfloat16(*)[72]>(smraw + VS_OFF);
    __nv_bfloat16 (*Bsm)[64][72] = reinterpret_cast<__nv_bfloat16(*)[64][72]>(smraw + BS_OFF);

    const int bh = blockIdx.x;
    const int b = bh >> 2, h = bh & 3;
    const int tid = threadIdx.x, lane = tid & 31, warp = tid >> 5;
    const int g = lane >> 2, tig = lane & 3;
    const int li = lane & 7, sel = lane >> 3, l16 = lane & 15;
    const float* src = bs + (size_t)b * NS * ND;

    // ---------------- Phase 1: build Es once ------------------------------
    // column for this thread is FIXED: c = (tid & 63)*4  (512 % 64 == 0)
    {
        const int c = (tid & 63) << 2;
        float4 av = *reinterpret_cast<const float4*>(&obj[g_rank[b] * ND + c]);
        float sc = scale[0];
        av.x *= sc; av.y *= sc; av.z *= sc; av.w *= sc;
        #pragma unroll 8
        for (int i = 0; i < 32; i++) {
            int row = i * 8 + (tid >> 6);
            float4 x = *reinterpret_cast<const float4*>(src + row * ND + c);
            uint2 pk;
            pk.x = packbf(x.x + av.x, x.y + av.y);
            pk.y = packbf(x.z + av.z, x.w + av.w);
            *reinterpret_cast<uint2*>(&Es[row][c]) = pk;
        }
    }
    __syncthreads();

    // ---------------- Phase 2: K & V GEMMs (one Es pass) ------------------
    float accK[8][4], accV[8][4];
    #pragma unroll
    for (int j = 0; j < 8; j++)
        #pragma unroll
        for (int c = 0; c < 4; c++) { accK[j][c] = 0.f; accV[j][c] = 0.f; }

    #pragma unroll 1
    for (int kq = 0; kq < 4; kq++) {            // 64 k-cols per chunk
        __syncthreads();
        // stage K and V weight slices for this k-chunk (16 KB, cp.async)
        #pragma unroll
        for (int rep = 0; rep < 2; rep++) {      // rep==mat: 0=K,1=V
            int rem = tid;                       // [0,512)
            int r = rem >> 3, c = (rem & 7) * 8;
            int grow = (rep + 1) * 256 + h * DH + r;
            cpa16(sptr(&Bsm[rep][r][c]), &g_WqkvT[(size_t)grow * ND + kq * 64 + c]);
        }
        cpcommit();
        cpwait<0>();
        __syncthreads();
        #pragma unroll
        for (int ks = 0; ks < 4; ks++) {
            uint32_t a[4];
            ldm_x4(a, sptr(&Es[warp * 16 + (sel & 1) * 8 + li][kq * 64 + ks * 16 + (sel >> 1) * 8]));
            #pragma unroll
            for (int nj = 0; nj < 8; nj++) {
                uint32_t bf0[2], bf1[2];
                ldm_x2(bf0, sptr(&Bsm[0][nj * 8 + li][ks * 16 + (l16 >> 3) * 8]));
                mma16816(accK[nj], a, bf0);
                ldm_x2(bf1, sptr(&Bsm[1][nj * 8 + li][ks * 16 + (l16 >> 3) * 8]));
                mma16816(accV[nj], a, bf1);
            }
        }
    }
    // epilogue: bias + write K,V to smem (each warp owns its 16 rows)
    #pragma unroll
    for (int nj = 0; nj < 8; nj++)
        #pragma unroll
        for (int p = 0; p < 2; p++) {
            int row = warp * 16 + p * 8 + g;
            int col = nj * 8 + tig * 2;
            float bk0 = bk[h * DH + col], bk1 = bk[h * DH + col + 1];
            float bv0 = bv[h * DH + col], bv1 = bv[h * DH + col + 1];
            *reinterpret_cast<__nv_bfloat162*>(&Ks[row][col]) =
                __floats2bfloat162_rn(accK[nj][p * 2] + bk0, accK[nj][p * 2 + 1] + bk1);
            *reinterpret_cast<__nv_bfloat162*>(&Vs[row][col]) =
                __floats2bfloat162_rn(accV[nj][p * 2] + bv0, accV[nj][p * 2 + 1] + bv1);
        }

    // ---------------- Phase 3: Q GEMM -------------------------------------
    float accQ[8][4];
    #pragma unroll
    for (int j = 0; j < 8; j++)
        #pragma unroll
        for (int c = 0; c < 4; c++) accQ[j][c] = 0.f;

    #pragma unroll 1
    for (int kq = 0; kq < 4; kq++) {
        __syncthreads();
        {
            int r = tid >> 3, c = (tid & 7) * 8;
            int grow = h * DH + r;               // Q slice (mat 0)
            cpa16(sptr(&Bsm[0][r][c]), &g_WqkvT[(size_t)grow * ND + kq * 64 + c]);
        }
        cpcommit();
        cpwait<0>();
        __syncthreads();
        #pragma unroll
        for (int ks = 0; ks < 4; ks++) {
            uint32_t a[4];
            ldm_x4(a, sptr(&Es[warp * 16 + (sel & 1) * 8 + li][kq * 64 + ks * 16 + (sel >> 1) * 8]));
            #pragma unroll
            for (int nj = 0; nj < 8; nj++) {
                uint32_t bf0[2];
                ldm_x2(bf0, sptr(&Bsm[0][nj * 8 + li][ks * 16 + (l16 >> 3) * 8]));
                mma16816(accQ[nj], a, bf0);
            }
        }
    }
    // pack Q into A-fragments (bias folded in)
    uint32_t qf[4][4];
    #pragma unroll
    for (int kd = 0; kd < 4; kd++) {
        float b0 = bq[h * DH + kd * 16 + tig * 2];
        float b1 = bq[h * DH + kd * 16 + tig * 2 + 1];
        float b2 = bq[h * DH + kd * 16 + 8 + tig * 2];
        float b3 = bq[h * DH + kd * 16 + 8 + tig * 2 + 1];
        qf[kd][0] = packbf(accQ[2 * kd][0] + b0, accQ[2 * kd][1] + b1);
        qf[kd][1] = packbf(accQ[2 * kd][2] + b0, accQ[2 * kd][3] + b1);
        qf[kd][2] = packbf(accQ[2 * kd + 1][0] + b2, accQ[2 * kd + 1][1] + b3);
        qf[kd][3] = packbf(accQ[2 * kd + 1][2] + b2, accQ[2 * kd + 1][3] + b3);
    }
    __syncthreads();    // K/V smem writes visible to all warps

    // ---------------- Phase 4: flash attention ----------------------------
    float O[8][4];
    #pragma unroll
    for (int j = 0; j < 8; j++)
        #pragma unroll
        for (int c = 0; c < 4; c++) O[j][c] = 0.f;
    float mrow[2] = {-1e30f, -1e30f};
    float lrow[2] = {0.f, 0.f};
    const float SC = 0.125f * 1.4426950408889634f;

    #pragma unroll 1
    for (int kc = 0; kc < 4; kc++) {
        float s[8][4];
        #pragma unroll
        for (int j = 0; j < 8; j++)
            #pragma unroll
            for (int c = 0; c < 4; c++) s[j][c] = 0.f;

        #pragma unroll
        for (int kd = 0; kd < 4; kd++)
            #pragma unroll
            for (int nj = 0; nj < 8; nj++) {
                uint32_t bfr[2];
                ldm_x2(bfr, sptr(&Ks[kc * 64 + nj * 8 + li][kd * 16 + (l16 >> 3) * 8]));
                mma16816(s[nj], qf[kd], bfr);
            }

        #pragma unroll
        for (int rs = 0; rs < 2; rs++) {
            float mx = -1e30f;
            #pragma unroll
            for (int nj = 0; nj < 8; nj++)
                mx = fmaxf(mx, fmaxf(s[nj][rs * 2], s[nj][rs * 2 + 1]));
            mx = fmaxf(mx, __shfl_xor_sync(0xffffffffu, mx, 1));
            mx = fmaxf(mx, __shfl_xor_sync(0xffffffffu, mx, 2));
            float mnew = fmaxf(mrow[rs], mx);
            float alpha = fexp2((mrow[rs] - mnew) * SC);
            mrow[rs] = mnew;
            float sum = 0.f;
            #pragma unroll
            for (int nj = 0; nj < 8; nj++) {
                float p0 = fexp2((s[nj][rs * 2]     - mnew) * SC);
                float p1 = fexp2((s[nj][rs * 2 + 1] - mnew) * SC);
                s[nj][rs * 2] = p0;
                s[nj][rs * 2 + 1] = p1;
                sum += p0 + p1;
            }
            sum += __shfl_xor_sync(0xffffffffu, sum, 1);
            sum += __shfl_xor_sync(0xffffffffu, sum, 2);
            lrow[rs] = lrow[rs] * alpha + sum;
            #pragma unroll
            for (int nj = 0; nj < 8; nj++) {
                O[nj][rs * 2]     *= alpha;
                O[nj][rs * 2 + 1] *= alpha;
            }
        }

        #pragma unroll
        for (int kk = 0; kk < 4; kk++) {
            uint32_t pa[4];
            pa[0] = packbf(s[2 * kk][0],     s[2 * kk][1]);
            pa[1] = packbf(s[2 * kk][2],     s[2 * kk][3]);
            pa[2] = packbf(s[2 * kk + 1][0], s[2 * kk + 1][1]);
            pa[3] = packbf(s[2 * kk + 1][2], s[2 * kk + 1][3]);
            #pragma unroll
            for (int nj = 0; nj < 8; nj++) {
                uint32_t bv2[2];
                ldm_x2t(bv2, sptr(&Vs[kc * 64 + kk * 16 + l16][nj * 8]));
                mma16816(O[nj], pa, bv2);
            }
        }
    }

    // write ctx
    #pragma unroll
    for (int rs = 0; rs < 2; rs++) {
        float inv = 1.f / lrow[rs];
        int row = warp * 16 + rs * 8 + g;
        #pragma unroll
        for (int nj = 0; nj < 8; nj++) {
            int col = nj * 8 + tig * 2;
            *reinterpret_cast<__nv_bfloat162*>(
                &g_ctx[((size_t)b * NS + row) * ND + h * DH + col]) =
                __floats2bfloat162_rn(O[nj][rs * 2] * inv, O[nj][rs * 2 + 1] * inv);
        }
    }
}

// ---------------------------------------------------------------------------
// Output projection: cp.async double-buffered 128x128x256 GEMM
// out = (gsize>1) ? batch_seq + ctx@Wo + bo : batch_seq
// ---------------------------------------------------------------------------
__global__ __launch_bounds__(256) void gemm_out(const float* __restrict__ bs,
                                                const float* __restrict__ bo,
                                                float* __restrict__ out) {
    __shared__ __nv_bfloat16 Asm[2][128][40];
    __shared__ __nv_bfloat16 Bsm[2][128][40];

    const int tid  = threadIdx.x;
    const int lane = tid & 31;
    const int warp = tid >> 5;
    const int wm = warp >> 1, wn = warp & 1;
    const int r0 = tid >> 2, c0 = (tid & 3) * 8;
    const int li = lane & 7, sel = lane >> 3, l16 = lane & 15;

    const int m0 = blockIdx.x * 128;
    const int n0 = blockIdx.y * 128;
    const __nv_bfloat16* A  = g_ctx + (size_t)m0 * 256;
    const __nv_bfloat16* Bt = g_WoT + (size_t)n0 * 256;

    float acc[2][8][4];
    #pragma unroll
    for (int i = 0; i < 2; i++)
        #pragma unroll
        for (int j = 0; j < 8; j++)
            #pragma unroll
            for (int c = 0; c < 4; c++) acc[i][j][c] = 0.f;

    auto stage = [&](int buf, int kt) {
        const __nv_bfloat16* Ag = A + kt * 32;
        const __nv_bfloat16* Bg = Bt + kt * 32;
        cpa16(sptr(&Asm[buf][r0][c0]),      &Ag[r0 * 256 + c0]);
        cpa16(sptr(&Asm[buf][r0 + 64][c0]), &Ag[(r0 + 64) * 256 + c0]);
        cpa16(sptr(&Bsm[buf][r0][c0]),      &Bg[r0 * 256 + c0]);
        cpa16(sptr(&Bsm[buf][r0 + 64][c0]), &Bg[(r0 + 64) * 256 + c0]);
        cpcommit();
    };

    stage(0, 0);
    #pragma unroll 1
    for (int kt = 0; kt < 8; kt++) {
        const int buf = kt & 1;
        if (kt < 7) {
            stage(buf ^ 1, kt + 1);
            cpwait<1>();
        } else {
            cpwait<0>();
        }
        __syncthreads();
        #pragma unroll
        for (int ks = 0; ks < 2; ks++) {
            uint32_t a[2][4];
            ldm_x4(a[0], sptr(&Asm[buf][wm * 32 +      li + (sel & 1) * 8][ks * 16 + (sel >> 1) * 8]));
            ldm_x4(a[1], sptr(&Asm[buf][wm * 32 + 16 + li + (sel & 1) * 8][ks * 16 + (sel >> 1) * 8]));
            #pragma unroll
            for (int nj = 0; nj < 8; nj++) {
                uint32_t bfr[2];
                ldm_x2(bfr, sptr(&Bsm[buf][wn * 64 + nj * 8 + li][ks * 16 + (l16 >> 3) * 8]));
                mma16816(acc[0][nj], a[0], bfr);
                mma16816(acc[1][nj], a[1], bfr);
            }
        }
        __syncthreads();
    }

    const int g = lane >> 2, tig = lane & 3;
    const int big = g_big[m0 >> 8];
    #pragma unroll
    for (int mi = 0; mi < 2; mi++)
        #pragma unroll
        for (int nj = 0; nj < 8; nj++)
            #pragma unroll
            for (int p = 0; p < 2; p++) {
                int m = m0 + wm * 32 + mi * 16 + p * 8 + g;
                int n = n0 + wn * 64 + nj * 8 + tig * 2;
                int idx = m * ND + n;
                float2 base = *reinterpret_cast<const float2*>(&bs[idx]);
                float2 o;
                if (big) {
                    o.x = base.x + acc[mi][nj][p * 2]     + bo[n];
                    o.y = base.y + acc[mi][nj][p * 2 + 1] + bo[n + 1];
                } else {
                    o = base;
                }
                *reinterpret_cast<float2*>(&out[idx]) = o;
            }
}

// ---------------------------------------------------------------------------
// Launch
// ---------------------------------------------------------------------------
extern "C" void kernel_launch(void* const* d_in, const int* in_sizes, int n_in,
                              void* d_out, int out_size) {
    const float* bs    = (const float*)d_in[0];
    const int*   ids   = (const int*)d_in[1];
    const float* Wq    = (const float*)d_in[2];
    const float* Wk    = (const float*)d_in[3];
    const float* Wv    = (const float*)d_in[4];
    const float* Wo    = (const float*)d_in[5];
    const float* bq    = (const float*)d_in[6];
    const float* bk    = (const float*)d_in[7];
    const float* bv    = (const float*)d_in[8];
    const float* bo    = (const float*)d_in[9];
    const float* obj   = (const float*)d_in[10];
    const float* scale = (const float*)d_in[11];
    const int max_obj = in_sizes[10] / ND;

    static bool configured = false;
    if (!configured) {
        cudaFuncSetAttribute(fused_bh, cudaFuncAttributeMaxDynamicSharedMemorySize, FUSED_SMEM);
        configured = true;
    }

    prep_rank<<<1, NB>>>(ids, max_obj);
    conv_weights<<<768, 256>>>(Wq, Wk, Wv, Wo);
    fused_bh<<<NB * NH, 512, FUSED_SMEM>>>(bs, obj, scale, bq, bk, bv);
    gemm_out<<<dim3(512, 2), 256>>>(bs, bo, (float*)d_out);
}

// round 5
// speedup vs baseline: 1.4182x; 1.0108x over previous
#include <cuda_runtime.h>
#include <cuda_bf16.h>
#include <cstdint>

#define NB 256
#define NS 256
#define ND 256
#define NH 4
#define DH 64

// ---------------------------------------------------------------------------
// Device scratch (~34.5 MB total)
// ---------------------------------------------------------------------------
__device__ __nv_bfloat16 g_ctx[NB * NS * ND];   // [b*s][d]
__device__ __nv_bfloat16 g_Wqkv[3 * ND * ND];   // K-major: [mat][k][n] (0=Q,1=K,2=V)
__device__ __nv_bfloat16 g_Wo[ND * ND];         // K-major: [k][n]
__device__ int g_rank[NB];
__device__ int g_big[NB];

// ---------------------------------------------------------------------------
// PTX helpers
// ---------------------------------------------------------------------------
__device__ __forceinline__ uint32_t sptr(const void* p) {
    return static_cast<uint32_t>(__cvta_generic_to_shared(p));
}
__device__ __forceinline__ void ldm_x4(uint32_t r[4], uint32_t a) {
    asm volatile("ldmatrix.sync.aligned.m8n8.x4.shared.b16 {%0,%1,%2,%3}, [%4];\n"
                 : "=r"(r[0]), "=r"(r[1]), "=r"(r[2]), "=r"(r[3]) : "r"(a));
}
__device__ __forceinline__ void ldm_x2(uint32_t r[2], uint32_t a) {
    asm volatile("ldmatrix.sync.aligned.m8n8.x2.shared.b16 {%0,%1}, [%2];\n"
                 : "=r"(r[0]), "=r"(r[1]) : "r"(a));
}
__device__ __forceinline__ void ldm_x2t(uint32_t r[2], uint32_t a) {
    asm volatile("ldmatrix.sync.aligned.m8n8.x2.trans.shared.b16 {%0,%1}, [%2];\n"
                 : "=r"(r[0]), "=r"(r[1]) : "r"(a));
}
__device__ __forceinline__ void mma16816(float c[4], const uint32_t a[4], const uint32_t b[2]) {
    asm volatile(
        "mma.sync.aligned.m16n8k16.row.col.f32.bf16.bf16.f32 "
        "{%0,%1,%2,%3}, {%4,%5,%6,%7}, {%8,%9}, {%0,%1,%2,%3};\n"
        : "+f"(c[0]), "+f"(c[1]), "+f"(c[2]), "+f"(c[3])
        : "r"(a[0]), "r"(a[1]), "r"(a[2]), "r"(a[3]), "r"(b[0]), "r"(b[1]));
}
__device__ __forceinline__ uint32_t packbf(float x, float y) {
    __nv_bfloat162 t = __floats2bfloat162_rn(x, y);
    return *reinterpret_cast<uint32_t*>(&t);
}
__device__ __forceinline__ float fexp2(float x) {
    float y;
    asm("ex2.approx.ftz.f32 %0, %1;" : "=f"(y) : "f"(x));
    return y;
}
__device__ __forceinline__ void cpa16(uint32_t dst, const void* src) {
    asm volatile("cp.async.ca.shared.global [%0], [%1], 16;\n" :: "r"(dst), "l"(src));
}
__device__ __forceinline__ void cpcommit() {
    asm volatile("cp.async.commit_group;\n");
}
template <int N> __device__ __forceinline__ void cpwait() {
    asm volatile("cp.async.wait_group %0;\n" :: "n"(N));
}

// ---------------------------------------------------------------------------
// prep kernels
// ---------------------------------------------------------------------------
__global__ void prep_rank(const int* __restrict__ ids, int max_obj) {
    __shared__ int sh[NB];
    int t = threadIdx.x;
    sh[t] = ids[t];
    __syncthreads();
    int id = sh[t];
    int rank = 0, size = 0;
    #pragma unroll 8
    for (int j = 0; j < NB; j++) {
        int same = (sh[j] == id);
        size += same;
        rank += (j < t) ? same : 0;
    }
    g_rank[t] = (rank < max_obj) ? rank : (max_obj - 1);
    g_big[t]  = (size > 1);
}

// Pure coalesced fp32 -> bf16 cast, original K-major layout kept
__global__ void cast_weights(const float* __restrict__ Wq, const float* __restrict__ Wk,
                             const float* __restrict__ Wv, const float* __restrict__ Wo) {
    int i = blockIdx.x * 256 + threadIdx.x;    // 65536 threads, 4 floats each
    int lin = i * 4;
    int mat = lin >> 16;
    int off = lin & 65535;
    const float* W = (mat == 0) ? Wq : ((mat == 1) ? Wk : ((mat == 2) ? Wv : Wo));
    float4 x = *reinterpret_cast<const float4*>(W + off);
    uint2 pk;
    pk.x = packbf(x.x, x.y);
    pk.y = packbf(x.z, x.w);
    __nv_bfloat16* dst = (mat < 3) ? (g_Wqkv + mat * 65536) : g_Wo;
    *reinterpret_cast<uint2*>(dst + off) = pk;
}

// ---------------------------------------------------------------------------
// Fused kernel: ONE block per batch b (grid 256), 512 threads = 16 warps.
// Es built once; loop over 4 heads: {KV GEMM, Q GEMM, flash attn, ctx write}.
// smem: Es[256][264] 135168 + Ks[256][72] 36864 + Vs[256][72] 36864
//       + Bsm[2][64][72] 18432 = 227328 B
// ---------------------------------------------------------------------------
#define ES_OFF 0
#define KS_OFF 135168
#define VS_OFF 172032
#define BS_OFF 208896
#define FUSED_SMEM 227328

__global__ __launch_bounds__(512, 1) void fused_b(const float* __restrict__ bs,
                                                  const float* __restrict__ obj,
                                                  const float* __restrict__ scale,
                                                  const float* __restrict__ bq,
                                                  const float* __restrict__ bk,
                                                  const float* __restrict__ bv) {
    extern __shared__ char smraw[];
    __nv_bfloat16 (*Es)[264]     = reinterpret_cast<__nv_bfloat16(*)[264]>(smraw + ES_OFF);
    __nv_bfloat16 (*Ks)[72]      = reinterpret_cast<__nv_bfloat16(*)[72]>(smraw + KS_OFF);
    __nv_bfloat16 (*Vs)[72]      = reinterpret_cast<__nv_bfloat16(*)[72]>(smraw + VS_OFF);
    __nv_bfloat16 (*Bsm)[64][72] = reinterpret_cast<__nv_bfloat16(*)[64][72]>(smraw + BS_OFF);

    const int b = blockIdx.x;
    const int tid = threadIdx.x, lane = tid & 31, warp = tid >> 5;
    const int g = lane >> 2, tig = lane & 3;
    const int li = lane & 7, sel = lane >> 3, l16 = lane & 15;
    const float* src = bs + (size_t)b * NS * ND;

    // ---------------- Phase 1: build Es ONCE per batch ---------------------
    {
        const int c = (tid & 63) << 2;
        float4 av = *reinterpret_cast<const float4*>(&obj[g_rank[b] * ND + c]);
        float sc = scale[0];
        av.x *= sc; av.y *= sc; av.z *= sc; av.w *= sc;
        #pragma unroll 8
        for (int i = 0; i < 32; i++) {
            int row = i * 8 + (tid >> 6);
            float4 x = *reinterpret_cast<const float4*>(src + row * ND + c);
            uint2 pk;
            pk.x = packbf(x.x + av.x, x.y + av.y);
            pk.y = packbf(x.z + av.z, x.w + av.w);
            *reinterpret_cast<uint2*>(&Es[row][c]) = pk;
        }
    }
    __syncthreads();

    // ---------------- Head loop -------------------------------------------
    #pragma unroll 1
    for (int h = 0; h < NH; h++) {

        // ---- K & V GEMMs (one Es pass, two accumulators) ----
        float accK[8][4], accV[8][4];
        #pragma unroll
        for (int j = 0; j < 8; j++)
            #pragma unroll
            for (int c = 0; c < 4; c++) { accK[j][c] = 0.f; accV[j][c] = 0.f; }

        #pragma unroll 1
        for (int kq = 0; kq < 4; kq++) {
            __syncthreads();
            // stage K,V weight chunks, K-major [k 0..63][n 0..63]
            #pragma unroll
            for (int mloc = 0; mloc < 2; mloc++) {
                int r = tid >> 3, c = (tid & 7) * 8;
                cpa16(sptr(&Bsm[mloc][r][c]),
                      &g_Wqkv[((mloc + 1) << 16) + (kq * 64 + r) * ND + h * DH + c]);
            }
            cpcommit();
            cpwait<0>();
            __syncthreads();
            #pragma unroll
            for (int ks = 0; ks < 4; ks++) {
                uint32_t a[4];
                ldm_x4(a, sptr(&Es[warp * 16 + (sel & 1) * 8 + li][kq * 64 + ks * 16 + (sel >> 1) * 8]));
                #pragma unroll
                for (int nj = 0; nj < 8; nj++) {
                    uint32_t bf0[2], bf1[2];
                    ldm_x2t(bf0, sptr(&Bsm[0][ks * 16 + l16][nj * 8]));
                    mma16816(accK[nj], a, bf0);
                    ldm_x2t(bf1, sptr(&Bsm[1][ks * 16 + l16][nj * 8]));
                    mma16816(accV[nj], a, bf1);
                }
            }
        }
        // epilogue: bias + write K,V to smem
        #pragma unroll
        for (int nj = 0; nj < 8; nj++)
            #pragma unroll
            for (int p = 0; p < 2; p++) {
                int row = warp * 16 + p * 8 + g;
                int col = nj * 8 + tig * 2;
                float bk0 = bk[h * DH + col], bk1 = bk[h * DH + col + 1];
                float bv0 = bv[h * DH + col], bv1 = bv[h * DH + col + 1];
                *reinterpret_cast<__nv_bfloat162*>(&Ks[row][col]) =
                    __floats2bfloat162_rn(accK[nj][p * 2] + bk0, accK[nj][p * 2 + 1] + bk1);
                *reinterpret_cast<__nv_bfloat162*>(&Vs[row][col]) =
                    __floats2bfloat162_rn(accV[nj][p * 2] + bv0, accV[nj][p * 2 + 1] + bv1);
            }

        // ---- Q GEMM ----
        float accQ[8][4];
        #pragma unroll
        for (int j = 0; j < 8; j++)
            #pragma unroll
            for (int c = 0; c < 4; c++) accQ[j][c] = 0.f;

        #pragma unroll 1
        for (int kq = 0; kq < 4; kq++) {
            __syncthreads();
            {
                int r = tid >> 3, c = (tid & 7) * 8;
                cpa16(sptr(&Bsm[0][r][c]),
                      &g_Wqkv[(kq * 64 + r) * ND + h * DH + c]);   // mat 0 = Q
            }
            cpcommit();
            cpwait<0>();
            __syncthreads();
            #pragma unroll
            for (int ks = 0; ks < 4; ks++) {
                uint32_t a[4];
                ldm_x4(a, sptr(&Es[warp * 16 + (sel & 1) * 8 + li][kq * 64 + ks * 16 + (sel >> 1) * 8]));
                #pragma unroll
                for (int nj = 0; nj < 8; nj++) {
                    uint32_t bf0[2];
                    ldm_x2t(bf0, sptr(&Bsm[0][ks * 16 + l16][nj * 8]));
                    mma16816(accQ[nj], a, bf0);
                }
            }
        }
        // pack Q into A-fragments (bias folded in)
        uint32_t qf[4][4];
        #pragma unroll
        for (int kd = 0; kd < 4; kd++) {
            float b0 = bq[h * DH + kd * 16 + tig * 2];
            float b1 = bq[h * DH + kd * 16 + tig * 2 + 1];
            float b2 = bq[h * DH + kd * 16 + 8 + tig * 2];
            float b3 = bq[h * DH + kd * 16 + 8 + tig * 2 + 1];
            qf[kd][0] = packbf(accQ[2 * kd][0] + b0, accQ[2 * kd][1] + b1);
            qf[kd][1] = packbf(accQ[2 * kd][2] + b0, accQ[2 * kd][3] + b1);
            qf[kd][2] = packbf(accQ[2 * kd + 1][0] + b2, accQ[2 * kd + 1][1] + b3);
            qf[kd][3] = packbf(accQ[2 * kd + 1][2] + b2, accQ[2 * kd + 1][3] + b3);
        }
        __syncthreads();    // K/V smem writes visible

        // ---- flash attention ----
        float O[8][4];
        #pragma unroll
        for (int j = 0; j < 8; j++)
            #pragma unroll
            for (int c = 0; c < 4; c++) O[j][c] = 0.f;
        float mrow[2] = {-1e30f, -1e30f};
        float lrow[2] = {0.f, 0.f};
        const float SC = 0.125f * 1.4426950408889634f;

        #pragma unroll 1
        for (int kc = 0; kc < 4; kc++) {
            float s[8][4];
            #pragma unroll
            for (int j = 0; j < 8; j++)
                #pragma unroll
                for (int c = 0; c < 4; c++) s[j][c] = 0.f;

            #pragma unroll
            for (int kd = 0; kd < 4; kd++)
                #pragma unroll
                for (int nj = 0; nj < 8; nj++) {
                    uint32_t bfr[2];
                    ldm_x2(bfr, sptr(&Ks[kc * 64 + nj * 8 + li][kd * 16 + (l16 >> 3) * 8]));
                    mma16816(s[nj], qf[kd], bfr);
                }

            #pragma unroll
            for (int rs = 0; rs < 2; rs++) {
                float mx = -1e30f;
                #pragma unroll
                for (int nj = 0; nj < 8; nj++)
                    mx = fmaxf(mx, fmaxf(s[nj][rs * 2], s[nj][rs * 2 + 1]));
                mx = fmaxf(mx, __shfl_xor_sync(0xffffffffu, mx, 1));
                mx = fmaxf(mx, __shfl_xor_sync(0xffffffffu, mx, 2));
                float mnew = fmaxf(mrow[rs], mx);
                float alpha = fexp2((mrow[rs] - mnew) * SC);
                mrow[rs] = mnew;
                float sum = 0.f;
                #pragma unroll
                for (int nj = 0; nj < 8; nj++) {
                    float p0 = fexp2((s[nj][rs * 2]     - mnew) * SC);
                    float p1 = fexp2((s[nj][rs * 2 + 1] - mnew) * SC);
                    s[nj][rs * 2] = p0;
                    s[nj][rs * 2 + 1] = p1;
                    sum += p0 + p1;
                }
                sum += __shfl_xor_sync(0xffffffffu, sum, 1);
                sum += __shfl_xor_sync(0xffffffffu, sum, 2);
                lrow[rs] = lrow[rs] * alpha + sum;
                #pragma unroll
                for (int nj = 0; nj < 8; nj++) {
                    O[nj][rs * 2]     *= alpha;
                    O[nj][rs * 2 + 1] *= alpha;
                }
            }

            #pragma unroll
            for (int kk = 0; kk < 4; kk++) {
                uint32_t pa[4];
                pa[0] = packbf(s[2 * kk][0],     s[2 * kk][1]);
                pa[1] = packbf(s[2 * kk][2],     s[2 * kk][3]);
                pa[2] = packbf(s[2 * kk + 1][0], s[2 * kk + 1][1]);
                pa[3] = packbf(s[2 * kk + 1][2], s[2 * kk + 1][3]);
                #pragma unroll
                for (int nj = 0; nj < 8; nj++) {
                    uint32_t bv2[2];
                    ldm_x2t(bv2, sptr(&Vs[kc * 64 + kk * 16 + l16][nj * 8]));
                    mma16816(O[nj], pa, bv2);
                }
            }
        }

        // write ctx for this head
        #pragma unroll
        for (int rs = 0; rs < 2; rs++) {
            float inv = 1.f / lrow[rs];
            int row = warp * 16 + rs * 8 + g;
            #pragma unroll
            for (int nj = 0; nj < 8; nj++) {
                int col = nj * 8 + tig * 2;
                *reinterpret_cast<__nv_bfloat162*>(
                    &g_ctx[((size_t)b * NS + row) * ND + h * DH + col]) =
                    __floats2bfloat162_rn(O[nj][rs * 2] * inv, O[nj][rs * 2 + 1] * inv);
            }
        }
    }
}

// ---------------------------------------------------------------------------
// Output projection: cp.async double-buffered 128x128x256 GEMM
// out = (gsize>1) ? batch_seq + ctx@Wo + bo : batch_seq
// B staged K-major [k][n] directly from g_Wo, consumed via ldmatrix.trans
// ---------------------------------------------------------------------------
__global__ __launch_bounds__(256) void gemm_out(const float* __restrict__ bs,
                                                const float* __restrict__ bo,
                                                float* __restrict__ out) {
    __shared__ __nv_bfloat16 Asm[2][128][40];
    __shared__ __nv_bfloat16 Bsm[2][32][136];

    const int tid  = threadIdx.x;
    const int lane = tid & 31;
    const int warp = tid >> 5;
    const int wm = warp >> 1, wn = warp & 1;
    const int r0 = tid >> 2, c0 = (tid & 3) * 8;
    const int li = lane & 7, sel = lane >> 3, l16 = lane & 15;

    const int m0 = blockIdx.x * 128;
    const int n0 = blockIdx.y * 128;
    const __nv_bfloat16* A = g_ctx + (size_t)m0 * 256;

    float acc[2][8][4];
    #pragma unroll
    for (int i = 0; i < 2; i++)
        #pragma unroll
        for (int j = 0; j < 8; j++)
            #pragma unroll
            for (int c = 0; c < 4; c++) acc[i][j][c] = 0.f;

    auto stage = [&](int buf, int kt) {
        const __nv_bfloat16* Ag = A + kt * 32;
        cpa16(sptr(&Asm[buf][r0][c0]),      &Ag[r0 * 256 + c0]);
        cpa16(sptr(&Asm[buf][r0 + 64][c0]), &Ag[(r0 + 64) * 256 + c0]);
        int br = tid >> 4, bc = (tid & 15) * 8;        // 16 rows x 128 cols / half
        cpa16(sptr(&Bsm[buf][br][bc]),      &g_Wo[(kt * 32 + br) * ND + n0 + bc]);
        cpa16(sptr(&Bsm[buf][br + 16][bc]), &g_Wo[(kt * 32 + br + 16) * ND + n0 + bc]);
        cpcommit();
    };

    stage(0, 0);
    #pragma unroll 1
    for (int kt = 0; kt < 8; kt++) {
        const int buf = kt & 1;
        if (kt < 7) {
            stage(buf ^ 1, kt + 1);
            cpwait<1>();
        } else {
            cpwait<0>();
        }
        __syncthreads();
        #pragma unroll
        for (int ks = 0; ks < 2; ks++) {
            uint32_t a[2][4];
            ldm_x4(a[0], sptr(&Asm[buf][wm * 32 +      li + (sel & 1) * 8][ks * 16 + (sel >> 1) * 8]));
            ldm_x4(a[1], sptr(&Asm[buf][wm * 32 + 16 + li + (sel & 1) * 8][ks * 16 + (sel >> 1) * 8]));
            #pragma unroll
            for (int nj = 0; nj < 8; nj++) {
                uint32_t bfr[2];
                ldm_x2t(bfr, sptr(&Bsm[buf][ks * 16 + l16][wn * 64 + nj * 8]));
                mma16816(acc[0][nj], a[0], bfr);
                mma16816(acc[1][nj], a[1], bfr);
            }
        }
        __syncthreads();
    }

    const int g = lane >> 2, tig = lane & 3;
    const int big = g_big[m0 >> 8];
    #pragma unroll
    for (int mi = 0; mi < 2; mi++)
        #pragma unroll
        for (int nj = 0; nj < 8; nj++)
            #pragma unroll
            for (int p = 0; p < 2; p++) {
                int m = m0 + wm * 32 + mi * 16 + p * 8 + g;
                int n = n0 + wn * 64 + nj * 8 + tig * 2;
                int idx = m * ND + n;
                float2 base = *reinterpret_cast<const float2*>(&bs[idx]);
                float2 o;
                if (big) {
                    o.x = base.x + acc[mi][nj][p * 2]     + bo[n];
                    o.y = base.y + acc[mi][nj][p * 2 + 1] + bo[n + 1];
                } else {
                    o = base;
                }
                *reinterpret_cast<float2*>(&out[idx]) = o;
            }
}

// ---------------------------------------------------------------------------
// Launch
// ---------------------------------------------------------------------------
extern "C" void kernel_launch(void* const* d_in, const int* in_sizes, int n_in,
                              void* d_out, int out_size) {
    const float* bs    = (const float*)d_in[0];
    const int*   ids   = (const int*)d_in[1];
    const float* Wq    = (const float*)d_in[2];
    const float* Wk    = (const float*)d_in[3];
    const float* Wv    = (const float*)d_in[4];
    const float* Wo    = (const float*)d_in[5];
    const float* bq    = (const float*)d_in[6];
    const float* bk    = (const float*)d_in[7];
    const float* bv    = (const float*)d_in[8];
    const float* bo    = (const float*)d_in[9];
    const float* obj   = (const float*)d_in[10];
    const float* scale = (const float*)d_in[11];
    const int max_obj = in_sizes[10] / ND;

    static bool configured = false;
    if (!configured) {
        cudaFuncSetAttribute(fused_b, cudaFuncAttributeMaxDynamicSharedMemorySize, FUSED_SMEM);
        configured = true;
    }

    prep_rank<<<1, NB>>>(ids, max_obj);
    cast_weights<<<256, 256>>>(Wq, Wk, Wv, Wo);
    fused_b<<<NB, 512, FUSED_SMEM>>>(bs, obj, scale, bq, bk, bv);
    gemm_out<<<dim3(512, 2), 256>>>(bs, bo, (float*)d_out);
}